// round 6
// baseline (speedup 1.0000x reference)
#include <cuda_runtime.h>
#include <cuda_bf16.h>
#include <cstdint>

// Problem constants (fixed by the reference)
#define BATCH    8192
#define ITEMS    10000
#define ITEMS4   (ITEMS / 4)   // 2500 float4 per row
#define TPB      256
#define GRID     1184          // 148 SMs x occ 8 -> persistent, single wave

// Scratch (allocation-free rule: __device__ globals). Counter starts at 0
// (zero-initialized device global) and is reset to 0 by the last CTA each
// call, so graph replays are deterministic.
__device__ float        g_row_loss[BATCH];
__device__ unsigned int g_done_ctr;

// ---------------------------------------------------------------------------
// Persistent kernel: each CTA loops over rows (row += GRID). Per row:
//   q = relu(dot(h,W)+b), nq = relu(dot(t,W)+b),
//   loss = is_done ? 0 : |r + disc*nq - q|.
// h/t are loaded with streaming hint (__ldcs, evict-first) so the 40 KB W
// vector stays L1-resident across all rows handled by the CTA.
// Last CTA to finish reduces all 8192 row losses in a fixed order.
// ---------------------------------------------------------------------------
__global__ __launch_bounds__(TPB, 8)
void dq_fused_kernel(const float* __restrict__ hidden,   // [B, ITEMS]
                     const float* __restrict__ target,   // [B, ITEMS]
                     const float* __restrict__ W,        // [ITEMS]
                     const float* __restrict__ bptr,     // [1]
                     const float* __restrict__ rewards,  // [B]
                     const float* __restrict__ discount, // scalar
                     const unsigned char* __restrict__ is_done, // [B] bool
                     float* __restrict__ out)
{
    const int tid  = threadIdx.x;
    const int warp = tid >> 5;
    const int lane = tid & 31;

    const float4* __restrict__ w4 = reinterpret_cast<const float4*>(W);

    __shared__ float s_q[8];
    __shared__ float s_n[8];

    for (int row = blockIdx.x; row < BATCH; row += GRID) {
        const float4* __restrict__ h4 =
            reinterpret_cast<const float4*>(hidden + (size_t)row * ITEMS);
        const float4* __restrict__ t4 =
            reinterpret_cast<const float4*>(target + (size_t)row * ITEMS);

        float qa = 0.0f;   // dot(hidden_row, W)
        float na = 0.0f;   // dot(target_row, W)

        // 2500 float4 per row / 256 threads: ~10 trips/thread.
        // Unroll-by-4 so ptxas front-batches ~12 independent LDG.128.
        #pragma unroll 4
        for (int i = tid; i < ITEMS4; i += TPB) {
            float4 h = __ldcs(&h4[i]);   // streaming: evict-first
            float4 t = __ldcs(&t4[i]);   // streaming: evict-first
            float4 w = __ldg(&w4[i]);    // keep L1-resident
            qa = fmaf(h.x, w.x, qa); qa = fmaf(h.y, w.y, qa);
            qa = fmaf(h.z, w.z, qa); qa = fmaf(h.w, w.w, qa);
            na = fmaf(t.x, w.x, na); na = fmaf(t.y, w.y, na);
            na = fmaf(t.z, w.z, na); na = fmaf(t.w, w.w, na);
        }

        // Warp reduction (both accumulators)
        #pragma unroll
        for (int off = 16; off > 0; off >>= 1) {
            qa += __shfl_down_sync(0xFFFFFFFFu, qa, off);
            na += __shfl_down_sync(0xFFFFFFFFu, na, off);
        }

        if (lane == 0) { s_q[warp] = qa; s_n[warp] = na; }
        __syncthreads();

        if (warp == 0) {
            qa = (lane < 8) ? s_q[lane] : 0.0f;
            na = (lane < 8) ? s_n[lane] : 0.0f;
            #pragma unroll
            for (int off = 4; off > 0; off >>= 1) {
                qa += __shfl_down_sync(0xFFFFFFFFu, qa, off);
                na += __shfl_down_sync(0xFFFFFFFFu, na, off);
            }
            if (lane == 0) {
                const float b = bptr[0];
                const float q  = fmaxf(qa + b, 0.0f);
                const float nq = fmaxf(na + b, 0.0f);
                float loss = fabsf(rewards[row] + discount[0] * nq - q);
                if (is_done[row]) loss = 0.0f;
                g_row_loss[row] = loss;
            }
        }
        __syncthreads();   // protect s_q/s_n reuse on next row
    }

    // ---- last-CTA-done final reduction (fixed-order, deterministic) ----
    __shared__ bool s_last;
    __threadfence();                       // make g_row_loss writes visible
    if (tid == 0) {
        unsigned int prev = atomicAdd(&g_done_ctr, 1u);
        s_last = (prev == (unsigned int)(GRID - 1));
    }
    __syncthreads();
    if (!s_last) return;

    // This CTA sums all BATCH losses in a fixed order.
    float acc = 0.0f;
    #pragma unroll
    for (int i = tid; i < BATCH; i += TPB)
        acc += g_row_loss[i];

    #pragma unroll
    for (int off = 16; off > 0; off >>= 1)
        acc += __shfl_down_sync(0xFFFFFFFFu, acc, off);

    __shared__ float s_f[8];
    if (lane == 0) s_f[warp] = acc;
    __syncthreads();

    if (warp == 0) {
        acc = (lane < 8) ? s_f[lane] : 0.0f;
        #pragma unroll
        for (int off = 4; off > 0; off >>= 1)
            acc += __shfl_down_sync(0xFFFFFFFFu, acc, off);
        if (lane == 0) {
            out[0] = acc / (float)BATCH;
            g_done_ctr = 0;                // reset for next graph replay
        }
    }
}

// ---------------------------------------------------------------------------
// Launch. Input order per metadata:
//   0 hidden_states [B*ITEMS] f32
//   1 actions       [B]       i32   (unused by the math)
//   2 rewards       [B]       f32
//   3 discount      [1]       f32
//   4 targetQs_s    [B*ITEMS] f32
//   5 is_done       [B]       bool
//   6 W             [ITEMS]   f32
//   7 b             [1]       f32
// ---------------------------------------------------------------------------
extern "C" void kernel_launch(void* const* d_in, const int* in_sizes, int n_in,
                              void* d_out, int out_size)
{
    const float* hidden   = (const float*)d_in[0];
    const float* rewards  = (const float*)d_in[2];
    const float* discount = (const float*)d_in[3];
    const float* target   = (const float*)d_in[4];
    const unsigned char* is_done = (const unsigned char*)d_in[5];
    const float* W        = (const float*)d_in[6];
    const float* b        = (const float*)d_in[7];
    float* out = (float*)d_out;

    dq_fused_kernel<<<GRID, TPB>>>(hidden, target, W, b,
                                   rewards, discount, is_done, out);
}

// round 8
// speedup vs baseline: 1.1342x; 1.1342x over previous
#include <cuda_runtime.h>
#include <cuda_bf16.h>
#include <cstdint>

// Problem constants (fixed by the reference)
#define BATCH    8192
#define ITEMS    10000
#define ITEMS4   (ITEMS / 4)   // 2500 float4 per row
#define TPB      256

// Per-row loss scratch (allocation-free rule: __device__ global)
__device__ float g_row_loss[BATCH];

// Streaming load: read-only + L1 no-allocate (keeps W resident in L1,
// saves L1tex fill bandwidth for the one-touch h/t streams).
__device__ __forceinline__ float4 ldg_stream(const float4* p) {
    float4 v;
    asm("ld.global.nc.L1::no_allocate.v4.f32 {%0,%1,%2,%3}, [%4];"
        : "=f"(v.x), "=f"(v.y), "=f"(v.z), "=f"(v.w)
        : "l"(p));
    return v;
}

// ---------------------------------------------------------------------------
// Kernel 1: one CTA per row. Computes q = relu(dot(h,W)+b),
// nq = relu(dot(t,W)+b), loss = is_done ? 0 : |r + disc*nq - q|.
// Both dot products fused in a single pass (h-row, t-row, W read together).
// ---------------------------------------------------------------------------
__global__ __launch_bounds__(TPB, 8)
void dq_row_kernel(const float* __restrict__ hidden,   // [B, ITEMS]
                   const float* __restrict__ target,   // [B, ITEMS]
                   const float* __restrict__ W,        // [ITEMS]
                   const float* __restrict__ bptr,     // [1]
                   const float* __restrict__ rewards,  // [B]
                   const float* __restrict__ discount, // scalar
                   const unsigned char* __restrict__ is_done) // [B] bool
{
    const int row = blockIdx.x;
    const int tid = threadIdx.x;

    const float4* __restrict__ h4 =
        reinterpret_cast<const float4*>(hidden + (size_t)row * ITEMS);
    const float4* __restrict__ t4 =
        reinterpret_cast<const float4*>(target + (size_t)row * ITEMS);
    const float4* __restrict__ w4 = reinterpret_cast<const float4*>(W);

    float qa = 0.0f;   // dot(hidden_row, W)
    float na = 0.0f;   // dot(target_row, W)

    // 2500 float4 per row / 256 threads -> ~10 trips/thread.
    #pragma unroll 2
    for (int i = tid; i < ITEMS4; i += TPB) {
        float4 h = ldg_stream(&h4[i]);   // L1 no-allocate stream
        float4 t = ldg_stream(&t4[i]);   // L1 no-allocate stream
        float4 w = __ldg(&w4[i]);        // L1-resident hot vector
        qa = fmaf(h.x, w.x, qa); qa = fmaf(h.y, w.y, qa);
        qa = fmaf(h.z, w.z, qa); qa = fmaf(h.w, w.w, qa);
        na = fmaf(t.x, w.x, na); na = fmaf(t.y, w.y, na);
        na = fmaf(t.z, w.z, na); na = fmaf(t.w, w.w, na);
    }

    // Warp reduction (two values at once)
    #pragma unroll
    for (int off = 16; off > 0; off >>= 1) {
        qa += __shfl_down_sync(0xFFFFFFFFu, qa, off);
        na += __shfl_down_sync(0xFFFFFFFFu, na, off);
    }

    __shared__ float s_q[8];
    __shared__ float s_n[8];
    const int warp = tid >> 5;
    const int lane = tid & 31;
    if (lane == 0) { s_q[warp] = qa; s_n[warp] = na; }
    __syncthreads();

    if (warp == 0) {
        qa = (lane < 8) ? s_q[lane] : 0.0f;
        na = (lane < 8) ? s_n[lane] : 0.0f;
        #pragma unroll
        for (int off = 4; off > 0; off >>= 1) {
            qa += __shfl_down_sync(0xFFFFFFFFu, qa, off);
            na += __shfl_down_sync(0xFFFFFFFFu, na, off);
        }
        if (lane == 0) {
            const float b = bptr[0];
            const float q  = fmaxf(qa + b, 0.0f);
            const float nq = fmaxf(na + b, 0.0f);
            float loss = fabsf(rewards[row] + discount[0] * nq - q);
            if (is_done[row]) loss = 0.0f;
            g_row_loss[row] = loss;
        }
    }
}

// ---------------------------------------------------------------------------
// Kernel 2: deterministic reduction of 8192 row losses -> out[0] = sum / B
// ---------------------------------------------------------------------------
__global__ __launch_bounds__(TPB, 1)
void dq_reduce_kernel(float* __restrict__ out)
{
    const int tid = threadIdx.x;
    float acc = 0.0f;
    #pragma unroll
    for (int i = tid; i < BATCH; i += TPB)
        acc += g_row_loss[i];

    #pragma unroll
    for (int off = 16; off > 0; off >>= 1)
        acc += __shfl_down_sync(0xFFFFFFFFu, acc, off);

    __shared__ float s[8];
    const int warp = tid >> 5;
    const int lane = tid & 31;
    if (lane == 0) s[warp] = acc;
    __syncthreads();

    if (warp == 0) {
        acc = (lane < 8) ? s[lane] : 0.0f;
        #pragma unroll
        for (int off = 4; off > 0; off >>= 1)
            acc += __shfl_down_sync(0xFFFFFFFFu, acc, off);
        if (lane == 0)
            out[0] = acc / (float)BATCH;
    }
}

// ---------------------------------------------------------------------------
// Launch. Input order per metadata:
//   0 hidden_states [B*ITEMS] f32
//   1 actions       [B]       i32   (unused by the math)
//   2 rewards       [B]       f32
//   3 discount      [1]       f32
//   4 targetQs_s    [B*ITEMS] f32
//   5 is_done       [B]       bool
//   6 W             [ITEMS]   f32
//   7 b             [1]       f32
// ---------------------------------------------------------------------------
extern "C" void kernel_launch(void* const* d_in, const int* in_sizes, int n_in,
                              void* d_out, int out_size)
{
    const float* hidden   = (const float*)d_in[0];
    const float* rewards  = (const float*)d_in[2];
    const float* discount = (const float*)d_in[3];
    const float* target   = (const float*)d_in[4];
    const unsigned char* is_done = (const unsigned char*)d_in[5];
    const float* W        = (const float*)d_in[6];
    const float* b        = (const float*)d_in[7];
    float* out = (float*)d_out;

    dq_row_kernel<<<BATCH, TPB>>>(hidden, target, W, b, rewards, discount, is_done);
    dq_reduce_kernel<<<1, TPB>>>(out);
}